// round 12
// baseline (speedup 1.0000x reference)
#include <cuda_runtime.h>
#include <cstdint>

#define HASH_SIZE (1u << 19)
#define HASH_MASK (HASH_SIZE - 1u)
#define PRIME_X 73856093u
#define PRIME_Y 19349663u
#define ROWS_PER_TILE 128      // 128 rows x 128B = 16KB per buffer
#define THREADS 128
#define UNROLL 8               // rows per thread-slot (128 thr, 8 thr/row, 16 groups)

// Persistent double-buffered pipeline:
//   buffer A bulk-storing  ||  buffer B gathering (cp.async, no result regs)
// cp.async breaks the register/MLP coupling (R4/R5); double buffering hides
// the bulk-store latency that R10's single-stage version exposed per tile.
__global__ void __launch_bounds__(THREADS)
hashgrid_gather_kernel(const float2* __restrict__ positions,
                       const float4* __restrict__ table,
                       float4* __restrict__ out,
                       int n) {
    __shared__ __align__(128) float4 buf[2][ROWS_PER_TILE * 8];  // 2 x 16 KB

    int tid  = threadIdx.x;
    int part = tid & 7;           // which float4 of the 128B row
    int lgrp = tid >> 3;          // local row group 0..15

    uint32_t sbase[2];
    sbase[0] = (uint32_t)__cvta_generic_to_shared(&buf[0][0]);
    sbase[1] = (uint32_t)__cvta_generic_to_shared(&buf[1][0]);

    int ntiles = (n + ROWS_PER_TILE - 1) / ROWS_PER_TILE;

    int it = 0;
    for (int t = blockIdx.x; t < ntiles; t += gridDim.x, ++it) {
        int stage = it & 1;

        // Before reusing this buffer, wait until the bulk store issued 2
        // iterations ago has finished READING smem (writes may still fly).
        if (it >= 2) {
            if (tid == 0)
                asm volatile("cp.async.bulk.wait_group.read 1;" ::: "memory");
            __syncthreads();
        }

        int base = t * ROWS_PER_TILE;

        int      r[UNROLL];
        float2   p[UNROLL];
        uint32_t h[UNROLL];

        // Phase 1: batch position loads (independent -> front-batched LDGs)
        #pragma unroll
        for (int u = 0; u < UNROLL; u++) {
            r[u] = base + lgrp + u * 16;
            if (r[u] < n) p[u] = __ldg(&positions[r[u]]);
        }

        // Phase 2: hashes. Low 19 bits of the int64 products depend only on
        // the low 32 bits -> uint32 math reproduces the reference exactly;
        // floorf is exact for uniform [0, 4096) positions.
        #pragma unroll
        for (int u = 0; u < UNROLL; u++) {
            uint32_t ix = (uint32_t)(int)floorf(p[u].x);
            uint32_t iy = (uint32_t)(int)floorf(p[u].y);
            h[u] = ((ix * PRIME_X) ^ (iy * PRIME_Y)) & HASH_MASK;
        }

        // Phase 3: 8 independent 16B cp.async gathers per thread
        #pragma unroll
        for (int u = 0; u < UNROLL; u++) {
            if (r[u] < n) {
                const float4* src = &table[(size_t)h[u] * 8 + part];
                uint32_t dst = sbase[stage] +
                               (uint32_t)(((lgrp + u * 16) * 8 + part) * 16);
                asm volatile("cp.async.cg.shared.global [%0], [%1], 16;"
                             :: "r"(dst), "l"(src));
            }
        }
        asm volatile("cp.async.commit_group;");
        asm volatile("cp.async.wait_group 0;");
        asm volatile("fence.proxy.async.shared::cta;" ::: "memory");
        __syncthreads();

        // Phase 4: bulk async store of the contiguous tile; do NOT wait —
        // completion overlaps the next iteration's gather phase.
        if (tid == 0) {
            int rows = n - base;
            rows = rows < ROWS_PER_TILE ? rows : ROWS_PER_TILE;
            if (rows > 0) {
                uint32_t bytes = (uint32_t)rows * 128u;
                asm volatile(
                    "cp.async.bulk.global.shared::cta.bulk_group [%0], [%1], %2;"
                    :: "l"(out + (size_t)base * 8), "r"(sbase[stage]), "r"(bytes)
                    : "memory");
                asm volatile("cp.async.bulk.commit_group;");
            }
        }
    }

    // Drain all outstanding bulk stores before block exit.
    if (tid == 0)
        asm volatile("cp.async.bulk.wait_group 0;" ::: "memory");
}

extern "C" void kernel_launch(void* const* d_in, const int* in_sizes, int n_in,
                              void* d_out, int out_size) {
    const float2* positions = (const float2*)d_in[0];   // [N, 2] float32
    const float4* table     = (const float4*)d_in[1];   // [HASH_SIZE, 32] float32
    float4* out             = (float4*)d_out;           // [N, 32] float32

    int n = in_sizes[0] / 2;    // N positions
    int ntiles = (n + ROWS_PER_TILE - 1) / ROWS_PER_TILE;

    // 7 blocks/SM (smem-limited: 2x16KB) x 148 SMs = persistent-ish grid
    int grid = 148 * 7;
    if (grid > ntiles) grid = ntiles;

    hashgrid_gather_kernel<<<grid, THREADS>>>(positions, table, out, n);
}

// round 13
// speedup vs baseline: 1.4467x; 1.4467x over previous
#include <cuda_runtime.h>
#include <cstdint>

#define HASH_SIZE (1u << 19)
#define HASH_MASK (HASH_SIZE - 1u)
#define PRIME_X 73856093u
#define PRIME_Y 19349663u
#define ROWS_PER_BLOCK 128     // 128 rows x 128B = 16KB smem -> 8 blocks/SM, 100% occ
#define THREADS 256
#define UNROLL 4               // 256 thr / 8 per row = 32 groups; 128 rows / 32 = 4

// One-shot blocks (R12 showed inter-block concurrency beats intra-block
// pipelining here). cp.async gathers (no result regs -> MLP free of the
// register coupling that capped R3-R5), staged in smem, one bulk store.
// 16KB tile -> 8 resident blocks/SM (vs R10's 6 at 32KB).
__global__ void __launch_bounds__(THREADS)
hashgrid_gather_kernel(const float2* __restrict__ positions,
                       const float4* __restrict__ table,
                       float4* __restrict__ out,
                       int n) {
    __shared__ __align__(128) float4 buf[ROWS_PER_BLOCK * 8];  // 16 KB

    int tid  = threadIdx.x;
    int part = tid & 7;           // which float4 of the 128B row
    int lgrp = tid >> 3;          // local row group 0..31
    int base = blockIdx.x * ROWS_PER_BLOCK;

    uint32_t smem_base = (uint32_t)__cvta_generic_to_shared(buf);

    int      r[UNROLL];
    float2   p[UNROLL];
    uint32_t h[UNROLL];

    // Phase 1: batch position loads (independent -> front-batched LDGs)
    #pragma unroll
    for (int u = 0; u < UNROLL; u++) {
        r[u] = base + lgrp + u * 32;
        if (r[u] < n) p[u] = __ldg(&positions[r[u]]);
    }

    // Phase 2: hashes. Low 19 bits of the int64 products depend only on the
    // low 32 bits -> uint32 math reproduces the reference exactly; floorf is
    // exact for uniform [0, 4096) positions.
    #pragma unroll
    for (int u = 0; u < UNROLL; u++) {
        uint32_t ix = (uint32_t)(int)floorf(p[u].x);
        uint32_t iy = (uint32_t)(int)floorf(p[u].y);
        h[u] = ((ix * PRIME_X) ^ (iy * PRIME_Y)) & HASH_MASK;
    }

    // Phase 3: 4 independent 16B cp.async gathers per thread (no result regs)
    #pragma unroll
    for (int u = 0; u < UNROLL; u++) {
        if (r[u] < n) {
            const float4* src = &table[(size_t)h[u] * 8 + part];
            uint32_t dst = smem_base + (uint32_t)(((lgrp + u * 32) * 8 + part) * 16);
            asm volatile("cp.async.cg.shared.global [%0], [%1], 16;"
                         :: "r"(dst), "l"(src));
        }
    }
    asm volatile("cp.async.commit_group;");
    asm volatile("cp.async.wait_group 0;");
    asm volatile("fence.proxy.async.shared::cta;" ::: "memory");
    __syncthreads();

    // Phase 4: single bulk async store of the contiguous tile. Wait only for
    // the smem READ side — the global-write tail overlaps the next block.
    if (tid == 0) {
        int rows = n - base;
        rows = rows < ROWS_PER_BLOCK ? rows : ROWS_PER_BLOCK;
        if (rows > 0) {
            uint32_t bytes = (uint32_t)rows * 128u;
            asm volatile("cp.async.bulk.global.shared::cta.bulk_group [%0], [%1], %2;"
                         :: "l"(out + (size_t)base * 8), "r"(smem_base), "r"(bytes)
                         : "memory");
            asm volatile("cp.async.bulk.commit_group;");
            asm volatile("cp.async.bulk.wait_group.read 0;" ::: "memory");
        }
    }
}

extern "C" void kernel_launch(void* const* d_in, const int* in_sizes, int n_in,
                              void* d_out, int out_size) {
    const float2* positions = (const float2*)d_in[0];   // [N, 2] float32
    const float4* table     = (const float4*)d_in[1];   // [HASH_SIZE, 32] float32
    float4* out             = (float4*)d_out;           // [N, 32] float32

    int n = in_sizes[0] / 2;    // N positions
    int grid = (n + ROWS_PER_BLOCK - 1) / ROWS_PER_BLOCK;

    hashgrid_gather_kernel<<<grid, THREADS>>>(positions, table, out, n);
}